// round 15
// baseline (speedup 1.0000x reference)
#include <cuda_runtime.h>
#include <cuda_fp16.h>
#include <cstdint>

// Problem constants
#define BATCH 2
#define SLEN  2048
#define DMODEL 4096
#define NHEAD 32
#define NKVH  8
#define HDIM  128
#define NTOK  (BATCH*SLEN)          // 4096
#define QKVW  6144                  // 4096 q + 1024 k + 1024 v
#define ATT_SCALE 0.08838834764831845f
#define LOSCALE 256.0f
#define INV_LOSCALE (1.0f / 256.0f)

// ---------------------------------------------------------------------------
// Scratch (allocation-free rule: __device__ globals)  — all fp16 now
// ---------------------------------------------------------------------------
__device__ __half g_xhi[(size_t)NTOK * DMODEL];
__device__ __half g_xlo[(size_t)NTOK * DMODEL];          // x256
__device__ __half g_whi[(size_t)QKVW * DMODEL];          // fused wq|wk|wv rows
__device__ __half g_wlo[(size_t)QKVW * DMODEL];          // x256
__device__ __half g_wohi[(size_t)DMODEL * DMODEL];
__device__ __half g_wolo[(size_t)DMODEL * DMODEL];       // x256
__device__ __half g_qkvhi[(size_t)NTOK * QKVW];          // unscaled (flash operands)
__device__ __half g_qkvlo[(size_t)NTOK * QKVW];          // unscaled
__device__ __half g_ahi[(size_t)NTOK * DMODEL];
__device__ __half g_alo[(size_t)NTOK * DMODEL];          // x256

// ---------------------------------------------------------------------------
// Helpers
// ---------------------------------------------------------------------------
__device__ __forceinline__ uint32_t smem_u32(const void* p) {
    uint32_t a;
    asm("{ .reg .u64 t; cvta.to.shared.u64 t, %1; cvt.u32.u64 %0, t; }" : "=r"(a) : "l"(p));
    return a;
}
__device__ __forceinline__ void cp16(uint32_t dst, const void* src) {
    asm volatile("cp.async.cg.shared.global [%0], [%1], 16;" :: "r"(dst), "l"(src));
}
__device__ __forceinline__ void ldsm_x4(uint32_t* r, uint32_t addr) {
    asm volatile("ldmatrix.sync.aligned.m8n8.x4.shared.b16 {%0,%1,%2,%3}, [%4];"
                 : "=r"(r[0]), "=r"(r[1]), "=r"(r[2]), "=r"(r[3]) : "r"(addr));
}
__device__ __forceinline__ void ldsm_x4t(uint32_t* r, uint32_t addr) {
    asm volatile("ldmatrix.sync.aligned.m8n8.x4.trans.shared.b16 {%0,%1,%2,%3}, [%4];"
                 : "=r"(r[0]), "=r"(r[1]), "=r"(r[2]), "=r"(r[3]) : "r"(addr));
}
// fp16 inputs, fp32 accumulate
__device__ __forceinline__ void mma_f32acc(float* d, const uint32_t* a, const uint32_t* b) {
    asm volatile("mma.sync.aligned.m16n8k16.row.col.f32.f16.f16.f32 "
                 "{%0,%1,%2,%3}, {%4,%5,%6,%7}, {%8,%9}, {%0,%1,%2,%3};"
                 : "+f"(d[0]), "+f"(d[1]), "+f"(d[2]), "+f"(d[3])
                 : "r"(a[0]), "r"(a[1]), "r"(a[2]), "r"(a[3]), "r"(b[0]), "r"(b[1]));
}
// fp16 inputs, fp16 accumulate (half-size acc: 2 regs = 4 halves)
__device__ __forceinline__ void mma_f16acc(uint32_t* d, const uint32_t* a, const uint32_t* b) {
    asm volatile("mma.sync.aligned.m16n8k16.row.col.f16.f16.f16.f16 "
                 "{%0,%1}, {%2,%3,%4,%5}, {%6,%7}, {%0,%1};"
                 : "+r"(d[0]), "+r"(d[1])
                 : "r"(a[0]), "r"(a[1]), "r"(a[2]), "r"(a[3]), "r"(b[0]), "r"(b[1]));
}
// split fp32 pair -> (hi u32 f16x2, lo u32 f16x2), lo scaled by ls
__device__ __forceinline__ uint32_t pack_hl(float f0, float f1, uint32_t& lo, float ls) {
    __half h0 = __float2half(f0), h1 = __float2half(f1);
    __half l0 = __float2half((f0 - __half2float(h0)) * ls);
    __half l1 = __float2half((f1 - __half2float(h1)) * ls);
    __half2 hp(h0, h1), lp(l0, l1);
    lo = *(uint32_t*)&lp;
    return *(uint32_t*)&hp;
}

// ---------------------------------------------------------------------------
// fp16 split HGEMM via mma.sync, templated warp microtile:
//   C = Ahi*Bhi^T (f32 acc) + [Ahi*Blo'^T + Alo'*Bhi^T] (f16 acc) / 256
// where lo' streams are pre-scaled x256 (keeps f16-acc products normal).
// Warp grid 2(m) x 4(n). Warp tile (MT*16) x (NG*16). BK=32, 3-stage pipeline.
// Optional fused interleaved RoPE + unscaled hi/lo fp16 epilogue (QKV path).
// ---------------------------------------------------------------------------
#define ROWB   80
#define NSTAGE 3

template<int MT, int NG>
__global__ __launch_bounds__(256, 1) void gemm_mma_split(
    const __half* __restrict__ Ahi, const __half* __restrict__ Alo,
    const __half* __restrict__ Bhi, const __half* __restrict__ Blo,
    float* __restrict__ C, __half* __restrict__ Chi, __half* __restrict__ Clo,
    const float* __restrict__ cosp, const float* __restrict__ sinp,
    int K, int ldc)
{
    constexpr int M_CTA = 2 * MT * 16;
    constexpr int N_CTA = 4 * NG * 16;
    constexpr int ABUF  = M_CTA * ROWB;
    constexpr int BBUF  = N_CTA * ROWB;
    constexpr int STAGEB = 2 * ABUF + 2 * BBUF;

    extern __shared__ char dynsm[];
    const uint32_t smb = smem_u32(dynsm);
    const int tid  = threadIdx.x;
    const int wid  = tid >> 5;
    const int lane = tid & 31;
    const int m0 = blockIdx.x * M_CTA;
    const int n0 = blockIdx.y * N_CTA;
    const int nch = K >> 5;

    auto load_stage = [&](int c, int st) {
        const uint32_t sb = smb + st * STAGEB;
#pragma unroll
        for (int i = 0; i < M_CTA / 64; i++) {
            int o = i * 256 + tid;
            int r = o >> 2, s = o & 3;
            size_t go = (size_t)(m0 + r) * K + c * 32 + s * 8;
            uint32_t so = r * ROWB + s * 16;
            cp16(sb + so,        Ahi + go);
            cp16(sb + ABUF + so, Alo + go);
        }
#pragma unroll
        for (int i = 0; i < N_CTA / 64; i++) {
            int o = i * 256 + tid;
            int r = o >> 2, s = o & 3;
            size_t go = (size_t)(n0 + r) * K + c * 32 + s * 8;
            uint32_t so = r * ROWB + s * 16;
            cp16(sb + 2 * ABUF + so,        Bhi + go);
            cp16(sb + 2 * ABUF + BBUF + so, Blo + go);
        }
        asm volatile("cp.async.commit_group;" ::: "memory");
    };

    float acc[MT][2 * NG][4];
    uint32_t crs[MT][2 * NG][2];
#pragma unroll
    for (int mt = 0; mt < MT; mt++)
#pragma unroll
        for (int nt = 0; nt < 2 * NG; nt++) {
#pragma unroll
            for (int q = 0; q < 4; q++) acc[mt][nt][q] = 0.f;
            crs[mt][nt][0] = 0u; crs[mt][nt][1] = 0u;
        }

    load_stage(0, 0);
    load_stage(1, 1);

    const int wm = (wid >> 2) * MT * 16;
    const int wn = (wid & 3) * NG * 16;
    const int arow = lane & 15, acolg = lane >> 4;
    const int brow = ((lane >> 4) << 3) + (lane & 7);
    const int bkof = ((lane >> 3) & 1) * 16;

    for (int c = 0; c < nch; c++) {
        if (c + 1 < nch) asm volatile("cp.async.wait_group 1;" ::: "memory");
        else             asm volatile("cp.async.wait_group 0;" ::: "memory");
        __syncthreads();
        if (c + 2 < nch) load_stage(c + 2, (c + 2) % NSTAGE);

        const uint32_t sb   = smb + (c % NSTAGE) * STAGEB;
        const uint32_t aHiB = sb;
        const uint32_t aLoB = sb + ABUF;
        const uint32_t bHiB = sb + 2 * ABUF;
        const uint32_t bLoB = sb + 2 * ABUF + BBUF;

#pragma unroll
        for (int ks = 0; ks < 2; ks++) {
            const int kb = ks * 32;
            uint32_t ah[MT][4], al[MT][4], bh[NG][4], bl[NG][4];
#pragma unroll
            for (int mt = 0; mt < MT; mt++) {
                uint32_t ao = (wm + mt * 16 + arow) * ROWB + kb + acolg * 16;
                ldsm_x4(ah[mt], aHiB + ao);
                ldsm_x4(al[mt], aLoB + ao);
            }
#pragma unroll
            for (int ng = 0; ng < NG; ng++) {
                uint32_t bo = (wn + ng * 16 + brow) * ROWB + kb + bkof;
                ldsm_x4(bh[ng], bHiB + bo);
                ldsm_x4(bl[ng], bLoB + bo);
            }
            // main term hh: f32 accumulate
#pragma unroll
            for (int mt = 0; mt < MT; mt++)
#pragma unroll
                for (int ng = 0; ng < NG; ng++) {
                    mma_f32acc(acc[mt][2 * ng],     ah[mt], bh[ng]);
                    mma_f32acc(acc[mt][2 * ng + 1], ah[mt], bh[ng] + 2);
                }
            // cross terms hl + lh: f16 accumulate (scaled x256)
#pragma unroll
            for (int mt = 0; mt < MT; mt++)
#pragma unroll
                for (int ng = 0; ng < NG; ng++) {
                    mma_f16acc(crs[mt][2 * ng],     ah[mt], bl[ng]);
                    mma_f16acc(crs[mt][2 * ng + 1], ah[mt], bl[ng] + 2);
                }
#pragma unroll
            for (int mt = 0; mt < MT; mt++)
#pragma unroll
                for (int ng = 0; ng < NG; ng++) {
                    mma_f16acc(crs[mt][2 * ng],     al[mt], bh[ng]);
                    mma_f16acc(crs[mt][2 * ng + 1], al[mt], bh[ng] + 2);
                }
        }
    }

#pragma unroll
    for (int mt = 0; mt < MT; mt++) {
        int r0 = m0 + wm + mt * 16 + (lane >> 2);
#pragma unroll
        for (int nt = 0; nt < 2 * NG; nt++) {
            int cc = n0 + wn + nt * 8 + (lane & 3) * 2;
            __half2 cr0 = *(__half2*)&crs[mt][nt][0];   // c0,c1 (row r0)
            __half2 cr1 = *(__half2*)&crs[mt][nt][1];   // c2,c3 (row r0+8)
            float v[4];
            v[0] = fmaf(__low2float(cr0),  INV_LOSCALE, acc[mt][nt][0]);
            v[1] = fmaf(__high2float(cr0), INV_LOSCALE, acc[mt][nt][1]);
            v[2] = fmaf(__low2float(cr1),  INV_LOSCALE, acc[mt][nt][2]);
            v[3] = fmaf(__high2float(cr1), INV_LOSCALE, acc[mt][nt][3]);
            if (Chi) {
                // fused interleaved RoPE on q (cols<4096) and k (4096..5119)
                if (cc < 5120) {
                    int p = (cc & 127) >> 1;
                    float c0 = cosp[(size_t)r0 * 64 + p];
                    float s0 = sinp[(size_t)r0 * 64 + p];
                    float c1 = cosp[(size_t)(r0 + 8) * 64 + p];
                    float s1 = sinp[(size_t)(r0 + 8) * 64 + p];
                    float t0 = v[0], t1 = v[1];
                    v[0] = t0 * c0 - t1 * s0;
                    v[1] = t0 * s0 + t1 * c0;
                    t0 = v[2]; t1 = v[3];
                    v[2] = t0 * c1 - t1 * s1;
                    v[3] = t0 * s1 + t1 * c1;
                }
                uint32_t lo0, lo1;   // flash operands: unscaled lo
                uint32_t hi0 = pack_hl(v[0], v[1], lo0, 1.0f);
                uint32_t hi1 = pack_hl(v[2], v[3], lo1, 1.0f);
                *(uint32_t*)(Chi + (size_t)r0 * ldc + cc)       = hi0;
                *(uint32_t*)(Clo + (size_t)r0 * ldc + cc)       = lo0;
                *(uint32_t*)(Chi + (size_t)(r0 + 8) * ldc + cc) = hi1;
                *(uint32_t*)(Clo + (size_t)(r0 + 8) * ldc + cc) = lo1;
            } else {
                *(float2*)(C + (size_t)r0 * ldc + cc)       = make_float2(v[0], v[1]);
                *(float2*)(C + (size_t)(r0 + 8) * ldc + cc) = make_float2(v[2], v[3]);
            }
        }
    }
}

// QKV: 128x192 tiles (MT=4, NG=3) -> grid (32, 32) = 1024 tiles
// OUT: 64x256 tiles  (MT=2, NG=4) -> grid (64, 16) = 1024 tiles
#define GSMEM_QKV (NSTAGE * (2 * 128 * ROWB + 2 * 192 * ROWB))   // 153600
#define GSMEM_OUT (NSTAGE * (2 * 64 * ROWB + 2 * 256 * ROWB))    // 153600

// ---------------------------------------------------------------------------
// fp32 -> fp16 hi/lo split (4 elems/thread), lo scaled x256
// ---------------------------------------------------------------------------
__global__ void split_f16(const float* __restrict__ src,
                          __half* __restrict__ hi,
                          __half* __restrict__ lo, int n)
{
    int i = (blockIdx.x * 256 + threadIdx.x) * 4;
    if (i >= n) return;
    float4 v = *(const float4*)(src + i);
    uint32_t l0, l1;
    uint32_t h0 = pack_hl(v.x, v.y, l0, LOSCALE);
    uint32_t h1 = pack_hl(v.z, v.w, l1, LOSCALE);
    *(uint2*)(hi + i) = make_uint2(h0, h1);
    *(uint2*)(lo + i) = make_uint2(l0, l1);
}

// ---------------------------------------------------------------------------
// Flash attention, tensor-core (fp16 3-term split, f32 acc), causal, GQA 4:1.
// Structure identical to validated R11/R14 kernel; dtype fp16, unscaled lo.
// Epilogue writes ahi (unscaled) / alo (x256, out-proj operand).
// ---------------------------------------------------------------------------
#define FROW    272
#define FQLO    (128 * FROW)
#define FSTAGE0 (2 * 128 * FROW)
#define FSTAGESZ (4 * 64 * FROW)
#define FK_HI 0
#define FK_LO (64 * FROW)
#define FV_HI (2 * 64 * FROW)
#define FV_LO (3 * 64 * FROW)
#define FSMEM (FSTAGE0 + 2 * FSTAGESZ)   // 208896 B

__global__ __launch_bounds__(256, 1) void flash_mma(
    const __half* __restrict__ qhi, const __half* __restrict__ qlo,
    __half* __restrict__ ohi_g, __half* __restrict__ olo_g)
{
    extern __shared__ char fsm[];
    const uint32_t smb = smem_u32(fsm);
    const int qt = 15 - (int)blockIdx.x;
    const int h  = blockIdx.y;
    const int b  = blockIdx.z;
    const int kvh = h >> 2;
    const int tid = threadIdx.x, wid = tid >> 5, lane = tid & 31;
    const int nkt = 2 * qt + 2;

    const size_t tokQ = (size_t)b * SLEN + (size_t)qt * 128;
    const __half* Qhg = qhi + tokQ * QKVW + h * HDIM;
    const __half* Qlg = qlo + tokQ * QKVW + h * HDIM;
    const size_t kvbase = (size_t)b * SLEN * QKVW + kvh * HDIM;
    const __half* Khg = qhi + kvbase + 4096;
    const __half* Klg = qlo + kvbase + 4096;
    const __half* Vhg = qhi + kvbase + 5120;
    const __half* Vlg = qlo + kvbase + 5120;

    auto load_kv = [&](int kt, int buf) {
        const uint32_t sb = smb + FSTAGE0 + buf * FSTAGESZ;
#pragma unroll
        for (int i = 0; i < 4; i++) {
            int ch = tid + i * 256;
            int r = ch >> 4, s = ch & 15;
            size_t go = (size_t)(kt * 64 + r) * QKVW + s * 8;
            uint32_t so = r * FROW + s * 16;
            cp16(sb + FK_HI + so, Khg + go);
            cp16(sb + FK_LO + so, Klg + go);
            cp16(sb + FV_HI + so, Vhg + go);
            cp16(sb + FV_LO + so, Vlg + go);
        }
        asm volatile("cp.async.commit_group;" ::: "memory");
    };

#pragma unroll
    for (int i = 0; i < 8; i++) {
        int ch = tid + i * 256;
        int r = ch >> 4, s = ch & 15;
        size_t go = (size_t)r * QKVW + s * 8;
        uint32_t so = r * FROW + s * 16;
        cp16(smb + so,        Qhg + go);
        cp16(smb + FQLO + so, Qlg + go);
    }
    load_kv(0, 0);
    load_kv(1, 1);

    float o[16][4];
#pragma unroll
    for (int ct = 0; ct < 16; ct++)
#pragma unroll
        for (int q = 0; q < 4; q++) o[ct][q] = 0.f;
    float m0 = -1e30f, m1 = -1e30f, l0 = 0.f, l1 = 0.f;

    const uint32_t aAddr0 = smb + (wid * 16 + (lane & 15)) * FROW + (lane >> 4) * 16;
    const int brow = ((lane >> 4) << 3) + (lane & 7);
    const int bkof = ((lane >> 3) & 1) * 16;
    const int vrowl = ((lane >> 3) & 1) * 8 + (lane & 7);
    const int vcof = ((lane >> 4) << 3) * 2;

    for (int kt = 0; kt < nkt; kt++) {
        if (kt + 1 < nkt) asm volatile("cp.async.wait_group 1;" ::: "memory");
        else              asm volatile("cp.async.wait_group 0;" ::: "memory");
        __syncthreads();

        const uint32_t Kb = smb + FSTAGE0 + (kt & 1) * FSTAGESZ;

        float s[8][4];
#pragma unroll
        for (int nt = 0; nt < 8; nt++)
#pragma unroll
            for (int q = 0; q < 4; q++) s[nt][q] = 0.f;

#pragma unroll
        for (int ks = 0; ks < 8; ks++) {
            uint32_t ah[4], al[4], bh[4][4], bl[4][4];
            ldsm_x4(ah, aAddr0 + ks * 32);
            ldsm_x4(al, aAddr0 + FQLO + ks * 32);
#pragma unroll
            for (int np = 0; np < 4; np++) {
                uint32_t ba = Kb + (np * 16 + brow) * FROW + ks * 32 + bkof;
                ldsm_x4(bh[np], ba + FK_HI);
                ldsm_x4(bl[np], ba + FK_LO);
            }
#pragma unroll
            for (int np = 0; np < 4; np++) {
                mma_f32acc(s[2 * np],     ah, bh[np]);
                mma_f32acc(s[2 * np + 1], ah, bh[np] + 2);
            }
#pragma unroll
            for (int np = 0; np < 4; np++) {
                mma_f32acc(s[2 * np],     ah, bl[np]);
                mma_f32acc(s[2 * np + 1], ah, bl[np] + 2);
            }
#pragma unroll
            for (int np = 0; np < 4; np++) {
                mma_f32acc(s[2 * np],     al, bh[np]);
                mma_f32acc(s[2 * np + 1], al, bh[np] + 2);
            }
        }

        const bool need_mask = (kt >= 2 * qt);
        const int rg0 = qt * 128 + wid * 16 + (lane >> 2);
#pragma unroll
        for (int nt = 0; nt < 8; nt++) {
#pragma unroll
            for (int q = 0; q < 4; q++) {
                float v = s[nt][q] * ATT_SCALE;
                if (need_mask) {
                    int col = kt * 64 + nt * 8 + (lane & 3) * 2 + (q & 1);
                    int row = rg0 + ((q >> 1) << 3);
                    if (col > row) v = -1e30f;
                }
                s[nt][q] = v;
            }
        }
        float mx0 = -1e30f, mx1 = -1e30f;
#pragma unroll
        for (int nt = 0; nt < 8; nt++) {
            mx0 = fmaxf(mx0, fmaxf(s[nt][0], s[nt][1]));
            mx1 = fmaxf(mx1, fmaxf(s[nt][2], s[nt][3]));
        }
        mx0 = fmaxf(mx0, __shfl_xor_sync(0xffffffffu, mx0, 1));
        mx0 = fmaxf(mx0, __shfl_xor_sync(0xffffffffu, mx0, 2));
        mx1 = fmaxf(mx1, __shfl_xor_sync(0xffffffffu, mx1, 1));
        mx1 = fmaxf(mx1, __shfl_xor_sync(0xffffffffu, mx1, 2));

        float mn0 = fmaxf(m0, mx0), mn1 = fmaxf(m1, mx1);
        float al0 = __expf(m0 - mn0), al1 = __expf(m1 - mn1);
        m0 = mn0; m1 = mn1;
        float rs0 = 0.f, rs1 = 0.f;
#pragma unroll
        for (int nt = 0; nt < 8; nt++) {
            float p0 = __expf(s[nt][0] - mn0);
            float p1 = __expf(s[nt][1] - mn0);
            float p2 = __expf(s[nt][2] - mn1);
            float p3 = __expf(s[nt][3] - mn1);
            s[nt][0] = p0; s[nt][1] = p1; s[nt][2] = p2; s[nt][3] = p3;
            rs0 += p0 + p1; rs1 += p2 + p3;
        }
        rs0 += __shfl_xor_sync(0xffffffffu, rs0, 1);
        rs0 += __shfl_xor_sync(0xffffffffu, rs0, 2);
        rs1 += __shfl_xor_sync(0xffffffffu, rs1, 1);
        rs1 += __shfl_xor_sync(0xffffffffu, rs1, 2);
        l0 = l0 * al0 + rs0;
        l1 = l1 * al1 + rs1;
#pragma unroll
        for (int ct = 0; ct < 16; ct++) {
            o[ct][0] *= al0; o[ct][1] *= al0;
            o[ct][2] *= al1; o[ct][3] *= al1;
        }

#pragma unroll
        for (int kj = 0; kj < 4; kj++) {
            uint32_t ph[4], pl[4];
            ph[0] = pack_hl(s[2 * kj][0],     s[2 * kj][1],     pl[0], 1.0f);
            ph[1] = pack_hl(s[2 * kj][2],     s[2 * kj][3],     pl[1], 1.0f);
            ph[2] = pack_hl(s[2 * kj + 1][0], s[2 * kj + 1][1], pl[2], 1.0f);
            ph[3] = pack_hl(s[2 * kj + 1][2], s[2 * kj + 1][3], pl[3], 1.0f);
            uint32_t vbase = Kb + (kj * 16 + vrowl) * FROW + vcof;
            uint32_t vh[8][4], vl[8][4];
#pragma unroll
            for (int cp2 = 0; cp2 < 8; cp2++) {
                uint32_t va = vbase + cp2 * 32;
                ldsm_x4t(vh[cp2], va + FV_HI);
                ldsm_x4t(vl[cp2], va + FV_LO);
            }
#pragma unroll
            for (int cp2 = 0; cp2 < 8; cp2++) {
                mma_f32acc(o[2 * cp2],     ph, vh[cp2]);
                mma_f32acc(o[2 * cp2 + 1], ph, vh[cp2] + 2);
            }
#pragma unroll
            for (int cp2 = 0; cp2 < 8; cp2++) {
                mma_f32acc(o[2 * cp2],     pl, vh[cp2]);
                mma_f32acc(o[2 * cp2 + 1], pl, vh[cp2] + 2);
            }
#pragma unroll
            for (int cp2 = 0; cp2 < 8; cp2++) {
                mma_f32acc(o[2 * cp2],     ph, vl[cp2]);
                mma_f32acc(o[2 * cp2 + 1], ph, vl[cp2] + 2);
            }
        }

        __syncthreads();
        if (kt + 2 < nkt) load_kv(kt + 2, kt & 1);
    }

    float inv0 = 1.0f / l0, inv1 = 1.0f / l1;
    size_t trow0 = (size_t)b * SLEN + qt * 128 + wid * 16 + (lane >> 2);
    int colb = h * HDIM + (lane & 3) * 2;
#pragma unroll
    for (int ct = 0; ct < 16; ct++) {
        int col = colb + ct * 8;
        uint32_t lo0, lo1;   // out-proj operand: lo scaled x256
        uint32_t hi0 = pack_hl(o[ct][0] * inv0, o[ct][1] * inv0, lo0, LOSCALE);
        uint32_t hi1 = pack_hl(o[ct][2] * inv1, o[ct][3] * inv1, lo1, LOSCALE);
        *(uint32_t*)(ohi_g + trow0 * DMODEL + col)       = hi0;
        *(uint32_t*)(olo_g + trow0 * DMODEL + col)       = lo0;
        *(uint32_t*)(ohi_g + (trow0 + 8) * DMODEL + col) = hi1;
        *(uint32_t*)(olo_g + (trow0 + 8) * DMODEL + col) = lo1;
    }
}

// ---------------------------------------------------------------------------
// Launch. inputs: 0=x 1=mask(all-true) 2=cos 3=sin 4=wq 5=wk 6=wv 7=wo
// ---------------------------------------------------------------------------
extern "C" void kernel_launch(void* const* d_in, const int* in_sizes, int n_in,
                              void* d_out, int out_size)
{
    const float* x    = (const float*)d_in[0];
    const float* cosp = (const float*)d_in[2];
    const float* sinp = (const float*)d_in[3];
    const float* wq   = (const float*)d_in[4];
    const float* wk   = (const float*)d_in[5];
    const float* wv   = (const float*)d_in[6];
    const float* wo   = (const float*)d_in[7];
    float* outp = (float*)d_out;

    __half *xhi, *xlo, *whi, *wlo, *wohi, *wolo, *qkvhi, *qkvlo, *ahi, *alo;
    cudaGetSymbolAddress((void**)&xhi,   g_xhi);
    cudaGetSymbolAddress((void**)&xlo,   g_xlo);
    cudaGetSymbolAddress((void**)&whi,   g_whi);
    cudaGetSymbolAddress((void**)&wlo,   g_wlo);
    cudaGetSymbolAddress((void**)&wohi,  g_wohi);
    cudaGetSymbolAddress((void**)&wolo,  g_wolo);
    cudaGetSymbolAddress((void**)&qkvhi, g_qkvhi);
    cudaGetSymbolAddress((void**)&qkvlo, g_qkvlo);
    cudaGetSymbolAddress((void**)&ahi,   g_ahi);
    cudaGetSymbolAddress((void**)&alo,   g_alo);

    cudaFuncSetAttribute(gemm_mma_split<4, 3>, cudaFuncAttributeMaxDynamicSharedMemorySize, GSMEM_QKV);
    cudaFuncSetAttribute(gemm_mma_split<2, 4>, cudaFuncAttributeMaxDynamicSharedMemorySize, GSMEM_OUT);
    cudaFuncSetAttribute(flash_mma, cudaFuncAttributeMaxDynamicSharedMemorySize, FSMEM);

    const int NX = NTOK * DMODEL;
    const int NW = DMODEL * DMODEL;
    const int NK = NKVH * HDIM * DMODEL;
    split_f16<<<NX / 1024, 256>>>(x,  xhi,  xlo,  NX);
    split_f16<<<NW / 1024, 256>>>(wq, whi,  wlo,  NW);
    split_f16<<<NK / 1024, 256>>>(wk, whi + (size_t)4096 * DMODEL, wlo + (size_t)4096 * DMODEL, NK);
    split_f16<<<NK / 1024, 256>>>(wv, whi + (size_t)5120 * DMODEL, wlo + (size_t)5120 * DMODEL, NK);
    split_f16<<<NW / 1024, 256>>>(wo, wohi, wolo, NW);

    // Fused QKV projection (+RoPE in epilogue) -> unscaled fp16 hi/lo
    gemm_mma_split<4, 3><<<dim3(NTOK / 128, QKVW / 192), 256, GSMEM_QKV>>>(
        xhi, xlo, whi, wlo, nullptr, qkvhi, qkvlo, cosp, sinp, DMODEL, QKVW);

    // Tensor-core causal GQA attention -> ahi / alo(x256)
    flash_mma<<<dim3(SLEN / 128, NHEAD, BATCH), 256, FSMEM>>>(qkvhi, qkvlo, ahi, alo);

    // Output projection -> fp32 d_out
    gemm_mma_split<2, 4><<<dim3(NTOK / 64, DMODEL / 256), 256, GSMEM_OUT>>>(
        ahi, alo, wohi, wolo, outp, nullptr, nullptr, nullptr, nullptr, DMODEL, DMODEL);
}

// round 16
// speedup vs baseline: 1.0906x; 1.0906x over previous
#include <cuda_runtime.h>
#include <cuda_fp16.h>
#include <cstdint>

// Problem constants
#define BATCH 2
#define SLEN  2048
#define DMODEL 4096
#define NHEAD 32
#define NKVH  8
#define HDIM  128
#define NTOK  (BATCH*SLEN)          // 4096
#define QKVW  6144                  // 4096 q + 1024 k + 1024 v
#define ATT_SCALE 0.08838834764831845f
#define LOSCALE 256.0f
#define INV_LOSCALE (1.0f / 256.0f)

// ---------------------------------------------------------------------------
// Scratch (allocation-free rule: __device__ globals)  — all fp16
// ---------------------------------------------------------------------------
__device__ __half g_xhi[(size_t)NTOK * DMODEL];
__device__ __half g_xlo[(size_t)NTOK * DMODEL];          // x256
__device__ __half g_whi[(size_t)QKVW * DMODEL];          // fused wq|wk|wv rows
__device__ __half g_wlo[(size_t)QKVW * DMODEL];          // x256
__device__ __half g_wohi[(size_t)DMODEL * DMODEL];
__device__ __half g_wolo[(size_t)DMODEL * DMODEL];       // x256
__device__ __half g_qkvhi[(size_t)NTOK * QKVW];          // unscaled (flash operands)
__device__ __half g_qkvlo[(size_t)NTOK * QKVW];          // unscaled
__device__ __half g_ahi[(size_t)NTOK * DMODEL];
__device__ __half g_alo[(size_t)NTOK * DMODEL];          // x256

// ---------------------------------------------------------------------------
// Helpers
// ---------------------------------------------------------------------------
__device__ __forceinline__ uint32_t smem_u32(const void* p) {
    uint32_t a;
    asm("{ .reg .u64 t; cvta.to.shared.u64 t, %1; cvt.u32.u64 %0, t; }" : "=r"(a) : "l"(p));
    return a;
}
__device__ __forceinline__ void cp16(uint32_t dst, const void* src) {
    asm volatile("cp.async.cg.shared.global [%0], [%1], 16;" :: "r"(dst), "l"(src));
}
__device__ __forceinline__ void ldsm_x4(uint32_t* r, uint32_t addr) {
    asm volatile("ldmatrix.sync.aligned.m8n8.x4.shared.b16 {%0,%1,%2,%3}, [%4];"
                 : "=r"(r[0]), "=r"(r[1]), "=r"(r[2]), "=r"(r[3]) : "r"(addr));
}
__device__ __forceinline__ void ldsm_x4t(uint32_t* r, uint32_t addr) {
    asm volatile("ldmatrix.sync.aligned.m8n8.x4.trans.shared.b16 {%0,%1,%2,%3}, [%4];"
                 : "=r"(r[0]), "=r"(r[1]), "=r"(r[2]), "=r"(r[3]) : "r"(addr));
}
// fp16 inputs, fp32 accumulate
__device__ __forceinline__ void mma_f32acc(float* d, const uint32_t* a, const uint32_t* b) {
    asm volatile("mma.sync.aligned.m16n8k16.row.col.f32.f16.f16.f32 "
                 "{%0,%1,%2,%3}, {%4,%5,%6,%7}, {%8,%9}, {%0,%1,%2,%3};"
                 : "+f"(d[0]), "+f"(d[1]), "+f"(d[2]), "+f"(d[3])
                 : "r"(a[0]), "r"(a[1]), "r"(a[2]), "r"(a[3]), "r"(b[0]), "r"(b[1]));
}
// fp16 inputs, fp16 accumulate (half-size acc: 2 regs = 4 halves)
__device__ __forceinline__ void mma_f16acc(uint32_t* d, const uint32_t* a, const uint32_t* b) {
    asm volatile("mma.sync.aligned.m16n8k16.row.col.f16.f16.f16.f16 "
                 "{%0,%1}, {%2,%3,%4,%5}, {%6,%7}, {%0,%1};"
                 : "+r"(d[0]), "+r"(d[1])
                 : "r"(a[0]), "r"(a[1]), "r"(a[2]), "r"(a[3]), "r"(b[0]), "r"(b[1]));
}
// split fp32 pair -> (hi u32 f16x2, lo u32 f16x2), lo scaled by ls
__device__ __forceinline__ uint32_t pack_hl(float f0, float f1, uint32_t& lo, float ls) {
    __half h0 = __float2half(f0), h1 = __float2half(f1);
    __half l0 = __float2half((f0 - __half2float(h0)) * ls);
    __half l1 = __float2half((f1 - __half2float(h1)) * ls);
    __half2 hp(h0, h1), lp(l0, l1);
    lo = *(uint32_t*)&lp;
    return *(uint32_t*)&hp;
}

// ---------------------------------------------------------------------------
// fp16 split HGEMM via mma.sync, templated warp microtile + term count:
//   TERMS=3: C = Ahi*Bhi^T (f32) + [Ahi*Blo'^T + Alo'*Bhi^T] (f16 acc) / 256
//   TERMS=2: C = Ahi*Bhi^T (f32) + [Ahi*Blo'^T] (f16 acc) / 256  (lh dropped)
// lo' streams pre-scaled x256. Warp grid 2(m) x 4(n). BK=32, 3-stage pipeline.
// Optional fused interleaved RoPE + unscaled hi/lo fp16 epilogue (QKV path).
// ---------------------------------------------------------------------------
#define ROWB   80
#define NSTAGE 3

template<int MT, int NG, int TERMS>
__global__ __launch_bounds__(256, 1) void gemm_mma_split(
    const __half* __restrict__ Ahi, const __half* __restrict__ Alo,
    const __half* __restrict__ Bhi, const __half* __restrict__ Blo,
    float* __restrict__ C, __half* __restrict__ Chi, __half* __restrict__ Clo,
    const float* __restrict__ cosp, const float* __restrict__ sinp,
    int K, int ldc)
{
    constexpr int M_CTA = 2 * MT * 16;
    constexpr int N_CTA = 4 * NG * 16;
    constexpr int ABUF  = M_CTA * ROWB;
    constexpr int BBUF  = N_CTA * ROWB;
    constexpr int STAGEB = 2 * ABUF + 2 * BBUF;

    extern __shared__ char dynsm[];
    const uint32_t smb = smem_u32(dynsm);
    const int tid  = threadIdx.x;
    const int wid  = tid >> 5;
    const int lane = tid & 31;
    const int m0 = blockIdx.x * M_CTA;
    const int n0 = blockIdx.y * N_CTA;
    const int nch = K >> 5;

    auto load_stage = [&](int c, int st) {
        const uint32_t sb = smb + st * STAGEB;
#pragma unroll
        for (int i = 0; i < M_CTA / 64; i++) {
            int o = i * 256 + tid;
            int r = o >> 2, s = o & 3;
            size_t go = (size_t)(m0 + r) * K + c * 32 + s * 8;
            uint32_t so = r * ROWB + s * 16;
            cp16(sb + so, Ahi + go);
            if (TERMS >= 3) cp16(sb + ABUF + so, Alo + go);
        }
#pragma unroll
        for (int i = 0; i < N_CTA / 64; i++) {
            int o = i * 256 + tid;
            int r = o >> 2, s = o & 3;
            size_t go = (size_t)(n0 + r) * K + c * 32 + s * 8;
            uint32_t so = r * ROWB + s * 16;
            cp16(sb + 2 * ABUF + so,        Bhi + go);
            cp16(sb + 2 * ABUF + BBUF + so, Blo + go);
        }
        asm volatile("cp.async.commit_group;" ::: "memory");
    };

    float acc[MT][2 * NG][4];
    uint32_t crs[MT][2 * NG][2];
#pragma unroll
    for (int mt = 0; mt < MT; mt++)
#pragma unroll
        for (int nt = 0; nt < 2 * NG; nt++) {
#pragma unroll
            for (int q = 0; q < 4; q++) acc[mt][nt][q] = 0.f;
            crs[mt][nt][0] = 0u; crs[mt][nt][1] = 0u;
        }

    load_stage(0, 0);
    load_stage(1, 1);

    const int wm = (wid >> 2) * MT * 16;
    const int wn = (wid & 3) * NG * 16;
    const int arow = lane & 15, acolg = lane >> 4;
    const int brow = ((lane >> 4) << 3) + (lane & 7);
    const int bkof = ((lane >> 3) & 1) * 16;

    for (int c = 0; c < nch; c++) {
        if (c + 1 < nch) asm volatile("cp.async.wait_group 1;" ::: "memory");
        else             asm volatile("cp.async.wait_group 0;" ::: "memory");
        __syncthreads();
        if (c + 2 < nch) load_stage(c + 2, (c + 2) % NSTAGE);

        const uint32_t sb   = smb + (c % NSTAGE) * STAGEB;
        const uint32_t aHiB = sb;
        const uint32_t aLoB = sb + ABUF;
        const uint32_t bHiB = sb + 2 * ABUF;
        const uint32_t bLoB = sb + 2 * ABUF + BBUF;

#pragma unroll
        for (int ks = 0; ks < 2; ks++) {
            const int kb = ks * 32;
            uint32_t ah[MT][4], al[MT][4], bh[NG][4], bl[NG][4];
#pragma unroll
            for (int mt = 0; mt < MT; mt++) {
                uint32_t ao = (wm + mt * 16 + arow) * ROWB + kb + acolg * 16;
                ldsm_x4(ah[mt], aHiB + ao);
                if (TERMS >= 3) ldsm_x4(al[mt], aLoB + ao);
            }
#pragma unroll
            for (int ng = 0; ng < NG; ng++) {
                uint32_t bo = (wn + ng * 16 + brow) * ROWB + kb + bkof;
                ldsm_x4(bh[ng], bHiB + bo);
                ldsm_x4(bl[ng], bLoB + bo);
            }
            // main term hh: f32 accumulate
#pragma unroll
            for (int mt = 0; mt < MT; mt++)
#pragma unroll
                for (int ng = 0; ng < NG; ng++) {
                    mma_f32acc(acc[mt][2 * ng],     ah[mt], bh[ng]);
                    mma_f32acc(acc[mt][2 * ng + 1], ah[mt], bh[ng] + 2);
                }
            // cross term hl: f16 accumulate (scaled x256)
#pragma unroll
            for (int mt = 0; mt < MT; mt++)
#pragma unroll
                for (int ng = 0; ng < NG; ng++) {
                    mma_f16acc(crs[mt][2 * ng],     ah[mt], bl[ng]);
                    mma_f16acc(crs[mt][2 * ng + 1], ah[mt], bl[ng] + 2);
                }
            // cross term lh: only in 3-term mode
            if (TERMS >= 3) {
#pragma unroll
                for (int mt = 0; mt < MT; mt++)
#pragma unroll
                    for (int ng = 0; ng < NG; ng++) {
                        mma_f16acc(crs[mt][2 * ng],     al[mt], bh[ng]);
                        mma_f16acc(crs[mt][2 * ng + 1], al[mt], bh[ng] + 2);
                    }
            }
        }
    }

#pragma unroll
    for (int mt = 0; mt < MT; mt++) {
        int r0 = m0 + wm + mt * 16 + (lane >> 2);
#pragma unroll
        for (int nt = 0; nt < 2 * NG; nt++) {
            int cc = n0 + wn + nt * 8 + (lane & 3) * 2;
            __half2 cr0 = *(__half2*)&crs[mt][nt][0];
            __half2 cr1 = *(__half2*)&crs[mt][nt][1];
            float v[4];
            v[0] = fmaf(__low2float(cr0),  INV_LOSCALE, acc[mt][nt][0]);
            v[1] = fmaf(__high2float(cr0), INV_LOSCALE, acc[mt][nt][1]);
            v[2] = fmaf(__low2float(cr1),  INV_LOSCALE, acc[mt][nt][2]);
            v[3] = fmaf(__high2float(cr1), INV_LOSCALE, acc[mt][nt][3]);
            if (Chi) {
                // fused interleaved RoPE on q (cols<4096) and k (4096..5119)
                if (cc < 5120) {
                    int p = (cc & 127) >> 1;
                    float c0 = cosp[(size_t)r0 * 64 + p];
                    float s0 = sinp[(size_t)r0 * 64 + p];
                    float c1 = cosp[(size_t)(r0 + 8) * 64 + p];
                    float s1 = sinp[(size_t)(r0 + 8) * 64 + p];
                    float t0 = v[0], t1 = v[1];
                    v[0] = t0 * c0 - t1 * s0;
                    v[1] = t0 * s0 + t1 * c0;
                    t0 = v[2]; t1 = v[3];
                    v[2] = t0 * c1 - t1 * s1;
                    v[3] = t0 * s1 + t1 * c1;
                }
                uint32_t lo0, lo1;   // flash operands: unscaled lo
                uint32_t hi0 = pack_hl(v[0], v[1], lo0, 1.0f);
                uint32_t hi1 = pack_hl(v[2], v[3], lo1, 1.0f);
                *(uint32_t*)(Chi + (size_t)r0 * ldc + cc)       = hi0;
                *(uint32_t*)(Clo + (size_t)r0 * ldc + cc)       = lo0;
                *(uint32_t*)(Chi + (size_t)(r0 + 8) * ldc + cc) = hi1;
                *(uint32_t*)(Clo + (size_t)(r0 + 8) * ldc + cc) = lo1;
            } else {
                *(float2*)(C + (size_t)r0 * ldc + cc)       = make_float2(v[0], v[1]);
                *(float2*)(C + (size_t)(r0 + 8) * ldc + cc) = make_float2(v[2], v[3]);
            }
        }
    }
}

// QKV: 128x192 tiles (MT=4, NG=3, 3 terms) -> grid (32, 32) = 1024 tiles
// OUT: 64x256 tiles  (MT=2, NG=4, 2 terms) -> grid (64, 16) = 1024 tiles
#define GSMEM_QKV (NSTAGE * (2 * 128 * ROWB + 2 * 192 * ROWB))   // 153600
#define GSMEM_OUT (NSTAGE * (2 * 64 * ROWB + 2 * 256 * ROWB))    // 153600

// ---------------------------------------------------------------------------
// fp32 -> fp16 hi/lo split (4 elems/thread), lo scaled x256
// ---------------------------------------------------------------------------
__global__ void split_f16(const float* __restrict__ src,
                          __half* __restrict__ hi,
                          __half* __restrict__ lo, int n)
{
    int i = (blockIdx.x * 256 + threadIdx.x) * 4;
    if (i >= n) return;
    float4 v = *(const float4*)(src + i);
    uint32_t l0, l1;
    uint32_t h0 = pack_hl(v.x, v.y, l0, LOSCALE);
    uint32_t h1 = pack_hl(v.z, v.w, l1, LOSCALE);
    *(uint2*)(hi + i) = make_uint2(h0, h1);
    *(uint2*)(lo + i) = make_uint2(l0, l1);
}

// ---------------------------------------------------------------------------
// Flash attention (fp16, causal, GQA 4:1):
//   S  = QhiKhi + QhiKlo + QloKhi  (3-term, f32 acc — logit errors amplify)
//   PV = PhiVhi + PloVhi           (2-term: Vlo dropped, ~1e-4 unamplified)
// Vlo tile no longer loaded (less smem traffic, fewer regs).
// ---------------------------------------------------------------------------
#define FROW    272
#define FQLO    (128 * FROW)
#define FSTAGE0 (2 * 128 * FROW)
#define FSTAGESZ (4 * 64 * FROW)
#define FK_HI 0
#define FK_LO (64 * FROW)
#define FV_HI (2 * 64 * FROW)
#define FSMEM (FSTAGE0 + 2 * FSTAGESZ)   // 208896 B

__global__ __launch_bounds__(256, 1) void flash_mma(
    const __half* __restrict__ qhi, const __half* __restrict__ qlo,
    __half* __restrict__ ohi_g, __half* __restrict__ olo_g)
{
    extern __shared__ char fsm[];
    const uint32_t smb = smem_u32(fsm);
    const int qt = 15 - (int)blockIdx.x;
    const int h  = blockIdx.y;
    const int b  = blockIdx.z;
    const int kvh = h >> 2;
    const int tid = threadIdx.x, wid = tid >> 5, lane = tid & 31;
    const int nkt = 2 * qt + 2;

    const size_t tokQ = (size_t)b * SLEN + (size_t)qt * 128;
    const __half* Qhg = qhi + tokQ * QKVW + h * HDIM;
    const __half* Qlg = qlo + tokQ * QKVW + h * HDIM;
    const size_t kvbase = (size_t)b * SLEN * QKVW + kvh * HDIM;
    const __half* Khg = qhi + kvbase + 4096;
    const __half* Klg = qlo + kvbase + 4096;
    const __half* Vhg = qhi + kvbase + 5120;

    auto load_kv = [&](int kt, int buf) {
        const uint32_t sb = smb + FSTAGE0 + buf * FSTAGESZ;
#pragma unroll
        for (int i = 0; i < 4; i++) {
            int ch = tid + i * 256;
            int r = ch >> 4, s = ch & 15;
            size_t go = (size_t)(kt * 64 + r) * QKVW + s * 8;
            uint32_t so = r * FROW + s * 16;
            cp16(sb + FK_HI + so, Khg + go);
            cp16(sb + FK_LO + so, Klg + go);
            cp16(sb + FV_HI + so, Vhg + go);
        }
        asm volatile("cp.async.commit_group;" ::: "memory");
    };

#pragma unroll
    for (int i = 0; i < 8; i++) {
        int ch = tid + i * 256;
        int r = ch >> 4, s = ch & 15;
        size_t go = (size_t)r * QKVW + s * 8;
        uint32_t so = r * FROW + s * 16;
        cp16(smb + so,        Qhg + go);
        cp16(smb + FQLO + so, Qlg + go);
    }
    load_kv(0, 0);
    load_kv(1, 1);

    float o[16][4];
#pragma unroll
    for (int ct = 0; ct < 16; ct++)
#pragma unroll
        for (int q = 0; q < 4; q++) o[ct][q] = 0.f;
    float m0 = -1e30f, m1 = -1e30f, l0 = 0.f, l1 = 0.f;

    const uint32_t aAddr0 = smb + (wid * 16 + (lane & 15)) * FROW + (lane >> 4) * 16;
    const int brow = ((lane >> 4) << 3) + (lane & 7);
    const int bkof = ((lane >> 3) & 1) * 16;
    const int vrowl = ((lane >> 3) & 1) * 8 + (lane & 7);
    const int vcof = ((lane >> 4) << 3) * 2;

    for (int kt = 0; kt < nkt; kt++) {
        if (kt + 1 < nkt) asm volatile("cp.async.wait_group 1;" ::: "memory");
        else              asm volatile("cp.async.wait_group 0;" ::: "memory");
        __syncthreads();

        const uint32_t Kb = smb + FSTAGE0 + (kt & 1) * FSTAGESZ;

        float s[8][4];
#pragma unroll
        for (int nt = 0; nt < 8; nt++)
#pragma unroll
            for (int q = 0; q < 4; q++) s[nt][q] = 0.f;

#pragma unroll
        for (int ks = 0; ks < 8; ks++) {
            uint32_t ah[4], al[4], bh[4][4], bl[4][4];
            ldsm_x4(ah, aAddr0 + ks * 32);
            ldsm_x4(al, aAddr0 + FQLO + ks * 32);
#pragma unroll
            for (int np = 0; np < 4; np++) {
                uint32_t ba = Kb + (np * 16 + brow) * FROW + ks * 32 + bkof;
                ldsm_x4(bh[np], ba + FK_HI);
                ldsm_x4(bl[np], ba + FK_LO);
            }
#pragma unroll
            for (int np = 0; np < 4; np++) {
                mma_f32acc(s[2 * np],     ah, bh[np]);
                mma_f32acc(s[2 * np + 1], ah, bh[np] + 2);
            }
#pragma unroll
            for (int np = 0; np < 4; np++) {
                mma_f32acc(s[2 * np],     ah, bl[np]);
                mma_f32acc(s[2 * np + 1], ah, bl[np] + 2);
            }
#pragma unroll
            for (int np = 0; np < 4; np++) {
                mma_f32acc(s[2 * np],     al, bh[np]);
                mma_f32acc(s[2 * np + 1], al, bh[np] + 2);
            }
        }

        const bool need_mask = (kt >= 2 * qt);
        const int rg0 = qt * 128 + wid * 16 + (lane >> 2);
#pragma unroll
        for (int nt = 0; nt < 8; nt++) {
#pragma unroll
            for (int q = 0; q < 4; q++) {
                float v = s[nt][q] * ATT_SCALE;
                if (need_mask) {
                    int col = kt * 64 + nt * 8 + (lane & 3) * 2 + (q & 1);
                    int row = rg0 + ((q >> 1) << 3);
                    if (col > row) v = -1e30f;
                }
                s[nt][q] = v;
            }
        }
        float mx0 = -1e30f, mx1 = -1e30f;
#pragma unroll
        for (int nt = 0; nt < 8; nt++) {
            mx0 = fmaxf(mx0, fmaxf(s[nt][0], s[nt][1]));
            mx1 = fmaxf(mx1, fmaxf(s[nt][2], s[nt][3]));
        }
        mx0 = fmaxf(mx0, __shfl_xor_sync(0xffffffffu, mx0, 1));
        mx0 = fmaxf(mx0, __shfl_xor_sync(0xffffffffu, mx0, 2));
        mx1 = fmaxf(mx1, __shfl_xor_sync(0xffffffffu, mx1, 1));
        mx1 = fmaxf(mx1, __shfl_xor_sync(0xffffffffu, mx1, 2));

        float mn0 = fmaxf(m0, mx0), mn1 = fmaxf(m1, mx1);
        float al0 = __expf(m0 - mn0), al1 = __expf(m1 - mn1);
        m0 = mn0; m1 = mn1;
        float rs0 = 0.f, rs1 = 0.f;
#pragma unroll
        for (int nt = 0; nt < 8; nt++) {
            float p0 = __expf(s[nt][0] - mn0);
            float p1 = __expf(s[nt][1] - mn0);
            float p2 = __expf(s[nt][2] - mn1);
            float p3 = __expf(s[nt][3] - mn1);
            s[nt][0] = p0; s[nt][1] = p1; s[nt][2] = p2; s[nt][3] = p3;
            rs0 += p0 + p1; rs1 += p2 + p3;
        }
        rs0 += __shfl_xor_sync(0xffffffffu, rs0, 1);
        rs0 += __shfl_xor_sync(0xffffffffu, rs0, 2);
        rs1 += __shfl_xor_sync(0xffffffffu, rs1, 1);
        rs1 += __shfl_xor_sync(0xffffffffu, rs1, 2);
        l0 = l0 * al0 + rs0;
        l1 = l1 * al1 + rs1;
#pragma unroll
        for (int ct = 0; ct < 16; ct++) {
            o[ct][0] *= al0; o[ct][1] *= al0;
            o[ct][2] *= al1; o[ct][3] *= al1;
        }

        // ---- PV: 2-term (PhiVhi + PloVhi), Vlo dropped ----
#pragma unroll
        for (int kj = 0; kj < 4; kj++) {
            uint32_t ph[4], pl[4];
            ph[0] = pack_hl(s[2 * kj][0],     s[2 * kj][1],     pl[0], 1.0f);
            ph[1] = pack_hl(s[2 * kj][2],     s[2 * kj][3],     pl[1], 1.0f);
            ph[2] = pack_hl(s[2 * kj + 1][0], s[2 * kj + 1][1], pl[2], 1.0f);
            ph[3] = pack_hl(s[2 * kj + 1][2], s[2 * kj + 1][3], pl[3], 1.0f);
            uint32_t vbase = Kb + (kj * 16 + vrowl) * FROW + vcof;
            uint32_t vh[8][4];
#pragma unroll
            for (int cp2 = 0; cp2 < 8; cp2++)
                ldsm_x4t(vh[cp2], vbase + cp2 * 32 + FV_HI);
#pragma unroll
            for (int cp2 = 0; cp2 < 8; cp2++) {
                mma_f32acc(o[2 * cp2],     ph, vh[cp2]);
                mma_f32acc(o[2 * cp2 + 1], ph, vh[cp2] + 2);
            }
#pragma unroll
            for (int cp2 = 0; cp2 < 8; cp2++) {
                mma_f32acc(o[2 * cp2],     pl, vh[cp2]);
                mma_f32acc(o[2 * cp2 + 1], pl, vh[cp2] + 2);
            }
        }

        __syncthreads();
        if (kt + 2 < nkt) load_kv(kt + 2, kt & 1);
    }

    float inv0 = 1.0f / l0, inv1 = 1.0f / l1;
    size_t trow0 = (size_t)b * SLEN + qt * 128 + wid * 16 + (lane >> 2);
    int colb = h * HDIM + (lane & 3) * 2;
#pragma unroll
    for (int ct = 0; ct < 16; ct++) {
        int col = colb + ct * 8;
        uint32_t lo0, lo1;   // out-proj operand: lo scaled x256
        uint32_t hi0 = pack_hl(o[ct][0] * inv0, o[ct][1] * inv0, lo0, LOSCALE);
        uint32_t hi1 = pack_hl(o[ct][2] * inv1, o[ct][3] * inv1, lo1, LOSCALE);
        *(uint32_t*)(ohi_g + trow0 * DMODEL + col)       = hi0;
        *(uint32_t*)(olo_g + trow0 * DMODEL + col)       = lo0;
        *(uint32_t*)(ohi_g + (trow0 + 8) * DMODEL + col) = hi1;
        *(uint32_t*)(olo_g + (trow0 + 8) * DMODEL + col) = lo1;
    }
}

// ---------------------------------------------------------------------------
// Launch. inputs: 0=x 1=mask(all-true) 2=cos 3=sin 4=wq 5=wk 6=wv 7=wo
// ---------------------------------------------------------------------------
extern "C" void kernel_launch(void* const* d_in, const int* in_sizes, int n_in,
                              void* d_out, int out_size)
{
    const float* x    = (const float*)d_in[0];
    const float* cosp = (const float*)d_in[2];
    const float* sinp = (const float*)d_in[3];
    const float* wq   = (const float*)d_in[4];
    const float* wk   = (const float*)d_in[5];
    const float* wv   = (const float*)d_in[6];
    const float* wo   = (const float*)d_in[7];
    float* outp = (float*)d_out;

    __half *xhi, *xlo, *whi, *wlo, *wohi, *wolo, *qkvhi, *qkvlo, *ahi, *alo;
    cudaGetSymbolAddress((void**)&xhi,   g_xhi);
    cudaGetSymbolAddress((void**)&xlo,   g_xlo);
    cudaGetSymbolAddress((void**)&whi,   g_whi);
    cudaGetSymbolAddress((void**)&wlo,   g_wlo);
    cudaGetSymbolAddress((void**)&wohi,  g_wohi);
    cudaGetSymbolAddress((void**)&wolo,  g_wolo);
    cudaGetSymbolAddress((void**)&qkvhi, g_qkvhi);
    cudaGetSymbolAddress((void**)&qkvlo, g_qkvlo);
    cudaGetSymbolAddress((void**)&ahi,   g_ahi);
    cudaGetSymbolAddress((void**)&alo,   g_alo);

    cudaFuncSetAttribute(gemm_mma_split<4, 3, 3>, cudaFuncAttributeMaxDynamicSharedMemorySize, GSMEM_QKV);
    cudaFuncSetAttribute(gemm_mma_split<2, 4, 2>, cudaFuncAttributeMaxDynamicSharedMemorySize, GSMEM_OUT);
    cudaFuncSetAttribute(flash_mma, cudaFuncAttributeMaxDynamicSharedMemorySize, FSMEM);

    const int NX = NTOK * DMODEL;
    const int NW = DMODEL * DMODEL;
    const int NK = NKVH * HDIM * DMODEL;
    split_f16<<<NX / 1024, 256>>>(x,  xhi,  xlo,  NX);
    split_f16<<<NW / 1024, 256>>>(wq, whi,  wlo,  NW);
    split_f16<<<NK / 1024, 256>>>(wk, whi + (size_t)4096 * DMODEL, wlo + (size_t)4096 * DMODEL, NK);
    split_f16<<<NK / 1024, 256>>>(wv, whi + (size_t)5120 * DMODEL, wlo + (size_t)5120 * DMODEL, NK);
    split_f16<<<NW / 1024, 256>>>(wo, wohi, wolo, NW);

    // Fused QKV projection (+RoPE in epilogue), 3-term -> unscaled fp16 hi/lo
    gemm_mma_split<4, 3, 3><<<dim3(NTOK / 128, QKVW / 192), 256, GSMEM_QKV>>>(
        xhi, xlo, whi, wlo, nullptr, qkvhi, qkvlo, cosp, sinp, DMODEL, QKVW);

    // Tensor-core causal GQA attention (S 3-term, PV 2-term) -> ahi / alo(x256)
    flash_mma<<<dim3(SLEN / 128, NHEAD, BATCH), 256, FSMEM>>>(qkvhi, qkvlo, ahi, alo);

    // Output projection, 2-term -> fp32 d_out
    gemm_mma_split<2, 4, 2><<<dim3(NTOK / 64, DMODEL / 256), 256, GSMEM_OUT>>>(
        ahi, alo, wohi, wolo, outp, nullptr, nullptr, nullptr, nullptr, DMODEL, DMODEL);
}